// round 4
// baseline (speedup 1.0000x reference)
#include <cuda_runtime.h>
#include <math.h>

#define D 128
#define MAXN 50048
#define MAXE 600064
#define TM 64
#define GEMM_SMEM ((256*128 + 256*TM) * 4)   // 192 KB: W1|W2 + transposed [agg|X] tile

// ---------------- device scratch (no allocations allowed) ----------------
__device__ float g_agg [(size_t)MAXN * D];
__device__ float g_bufA[(size_t)MAXN * D];
__device__ float g_bufB[(size_t)MAXN * D];
__device__ int   g_deg[MAXN];
__device__ int   g_off[MAXN + 1];
__device__ int   g_cursor[MAXN];
__device__ int   g_csr[MAXE];
__device__ int   g_bsum[256];
__device__ float g_invdeg[MAXN];

// buffer selectors: 0 = external pointer, 1 = g_bufA, 2 = g_bufB
static __device__ __forceinline__ const float* sel_src(const float* ext, int s) {
    return (s == 0) ? ext : ((s == 1) ? g_bufA : g_bufB);
}
static __device__ __forceinline__ float* sel_dst(float* ext, int s) {
    return (s == 0) ? ext : ((s == 1) ? g_bufA : g_bufB);
}

// ---------------- packed f32x2 helpers (FFMA2: 2x fp32 FMA throughput) ----
static __device__ __forceinline__ unsigned long long pk2(float x) {
    unsigned long long r;
    asm("mov.b64 %0, {%1, %1};" : "=l"(r) : "f"(x));
    return r;
}
static __device__ __forceinline__ void ffma2(unsigned long long& d,
                                             unsigned long long a,
                                             unsigned long long b) {
    asm("fma.rn.f32x2 %0, %1, %2, %0;" : "+l"(d) : "l"(a), "l"(b));
}
static __device__ __forceinline__ float2 upk(unsigned long long v) {
    float2 r;
    asm("mov.b64 {%0, %1}, %2;" : "=f"(r.x), "=f"(r.y) : "l"(v));
    return r;
}

// ---------------- CSR build ----------------
__global__ void zero_deg_kernel(int n) {
    int i = blockIdx.x * blockDim.x + threadIdx.x;
    if (i < n) g_deg[i] = 0;
}

__global__ void count_kernel(const int* __restrict__ dst, int e) {
    int i = blockIdx.x * blockDim.x + threadIdx.x;
    if (i < e) atomicAdd(&g_deg[dst[i]], 1);
}

// per-512-block exclusive scan over degrees; also emits inv_deg = 1/max(deg,1)
__global__ void scan_block_kernel(int n) {
    __shared__ int s[512];
    int t = threadIdx.x;
    int i = blockIdx.x * 512 + t;
    int v = (i < n) ? g_deg[i] : 0;
    if (i < n) g_invdeg[i] = 1.0f / fmaxf((float)v, 1.0f);
    s[t] = v;
    __syncthreads();
    #pragma unroll
    for (int d = 1; d < 512; d <<= 1) {
        int x = (t >= d) ? s[t - d] : 0;
        __syncthreads();
        s[t] += x;
        __syncthreads();
    }
    if (i < n) g_off[i] = s[t] - v;            // exclusive within block
    if (t == 511) g_bsum[blockIdx.x] = s[511]; // block total
}

// single-block parallel exclusive scan of block sums (nb <= 128)
__global__ void scan_spine_kernel(int nb) {
    __shared__ int s[128];
    int t = threadIdx.x;
    int v = (t < nb) ? g_bsum[t] : 0;
    s[t] = v;
    __syncthreads();
    #pragma unroll
    for (int d = 1; d < 128; d <<= 1) {
        int x = (t >= d) ? s[t - d] : 0;
        __syncthreads();
        s[t] += x;
        __syncthreads();
    }
    if (t < nb) g_bsum[t] = s[t] - v;          // exclusive
}

__global__ void scan_add_kernel(int n, int e) {
    int i = blockIdx.x * blockDim.x + threadIdx.x;
    if (i < n) {
        int o = g_off[i] + g_bsum[i >> 9];
        g_off[i] = o;
        g_cursor[i] = o;
    } else if (i == n) {
        g_off[n] = e;
    }
}

__global__ void fill_kernel(const int* __restrict__ src, const int* __restrict__ dst, int e) {
    int i = blockIdx.x * blockDim.x + threadIdx.x;
    if (i < e) {
        int d = dst[i];
        int p = atomicAdd(&g_cursor[d], 1);
        g_csr[p] = src[i];
    }
}

// ---------------- mean aggregation: one warp per node, float4 lanes --------
__global__ void agg_kernel(const float* __restrict__ Xext, int xsel, int n) {
    const float* X = sel_src(Xext, xsel);
    int warp = blockIdx.x * (blockDim.x >> 5) + (threadIdx.x >> 5);
    int lane = threadIdx.x & 31;
    if (warp >= n) return;
    int s = g_off[warp];
    int e = g_off[warp + 1];
    float4 acc = make_float4(0.f, 0.f, 0.f, 0.f);
    const float4* X4 = (const float4*)X;
    for (int k = s; k < e; k++) {
        int j = __ldg(&g_csr[k]);
        float4 v = __ldg(&X4[(size_t)j * 32 + lane]);
        acc.x += v.x; acc.y += v.y; acc.z += v.z; acc.w += v.w;
    }
    float sc = g_invdeg[warp];
    acc.x *= sc; acc.y *= sc; acc.z *= sc; acc.w *= sc;
    ((float4*)g_agg)[(size_t)warp * 32 + lane] = acc;
}

// ---------------- fused GEMM:  Y = ELU( agg@W1 + X@W2 + b ) ---------------
// CTA: 64 rows x 128 cols, K=256 (agg then X). Both weights + transposed
// input tile in SMEM. Thread micro-tile: 4 rows x 8 cols via FFMA2 pairs.
__global__ __launch_bounds__(256, 1) void gemm_elu_kernel(
    const float* __restrict__ Xext, int xsel,
    const float* __restrict__ W1, const float* __restrict__ W2,
    const float* __restrict__ bias,
    float* __restrict__ Yext, int ysel, int n)
{
    extern __shared__ float smem[];
    float* sW  = smem;                // [256][128] : k<128 -> W1 row k, else W2
    float* sIn = smem + 256 * 128;    // [256][TM]  : transposed [agg|X] tile

    const float* X = sel_src(Xext, xsel);
    float* Y = sel_dst(Yext, ysel);

    int t = threadIdx.x;
    int rowbase = blockIdx.x * TM;

    // ---- load weights (coalesced, conflict-free) ----
    {
        const float4* W1v = (const float4*)W1;
        const float4* W2v = (const float4*)W2;
        float4* sWv = (float4*)sW;
        #pragma unroll
        for (int i = 0; i < 16; i++) {
            int idx = t + i * 256;          // 0..4095
            sWv[idx]        = W1v[idx];
            sWv[idx + 4096] = W2v[idx];
        }
    }
    // ---- load input tiles transposed: sIn[k][m] ----
    // Lanes vary m (consecutive) with fixed kv -> STS conflict-free.
    // Global float4 loads are 512B-strided (L2-resident, acceptable).
    {
        #pragma unroll
        for (int i = 0; i < 16; i++) {
            int idx = t + i * 256;          // 0..4095
            int q   = idx >> 11;            // 0 = agg, 1 = X
            int rem = idx & 2047;
            int m   = rem & 63;             // lane-fastest -> conflict-free STS
            int kv  = rem >> 6;             // float4 column 0..31
            int row = rowbase + m;
            float4 v = make_float4(0.f, 0.f, 0.f, 0.f);
            const float* srcp = q ? X : g_agg;
            if (row < n) v = __ldg(&((const float4*)srcp)[(size_t)row * 32 + kv]);
            int kb = q * 128 + kv * 4;
            sIn[(kb + 0) * TM + m] = v.x;
            sIn[(kb + 1) * TM + m] = v.y;
            sIn[(kb + 2) * TM + m] = v.z;
            sIn[(kb + 3) * TM + m] = v.w;
        }
    }
    __syncthreads();

    int mrow = (t & 15) * 4;      // 4 rows
    int ncol = (t >> 4) * 8;      // 8 cols = 4 f32x2 pairs

    unsigned long long acc[4][4];
    #pragma unroll
    for (int r = 0; r < 4; r++)
        #pragma unroll
        for (int c = 0; c < 4; c++) acc[r][c] = 0ull;

    const float* aptr = sIn + mrow;
    const unsigned long long* wptr = (const unsigned long long*)(sW + ncol);

    #pragma unroll 4
    for (int k = 0; k < 256; k++) {
        float4 av = *(const float4*)aptr;
        unsigned long long a0 = pk2(av.x), a1 = pk2(av.y),
                           a2 = pk2(av.z), a3 = pk2(av.w);
        unsigned long long w0 = wptr[0], w1 = wptr[1],
                           w2 = wptr[2], w3 = wptr[3];
        ffma2(acc[0][0], a0, w0); ffma2(acc[0][1], a0, w1);
        ffma2(acc[0][2], a0, w2); ffma2(acc[0][3], a0, w3);
        ffma2(acc[1][0], a1, w0); ffma2(acc[1][1], a1, w1);
        ffma2(acc[1][2], a1, w2); ffma2(acc[1][3], a1, w3);
        ffma2(acc[2][0], a2, w0); ffma2(acc[2][1], a2, w1);
        ffma2(acc[2][2], a2, w2); ffma2(acc[2][3], a2, w3);
        ffma2(acc[3][0], a3, w0); ffma2(acc[3][1], a3, w1);
        ffma2(acc[3][2], a3, w2); ffma2(acc[3][3], a3, w3);
        aptr += TM;
        wptr += 64;   // 128 floats = 64 u64
    }

    // ---- epilogue: bias + ELU + store ----
    float b[8];
    #pragma unroll
    for (int j = 0; j < 8; j++) b[j] = __ldg(&bias[ncol + j]);

    #pragma unroll
    for (int r = 0; r < 4; r++) {
        int row = rowbase + mrow + r;
        if (row < n) {
            float o[8];
            #pragma unroll
            for (int c = 0; c < 4; c++) {
                float2 p = upk(acc[r][c]);
                o[2 * c]     = p.x + b[2 * c];
                o[2 * c + 1] = p.y + b[2 * c + 1];
            }
            #pragma unroll
            for (int j = 0; j < 8; j++) {
                float v = o[j];
                o[j] = (v > 0.f) ? v : expm1f(v);
            }
            float4* Yv = (float4*)(Y + (size_t)row * D + ncol);
            Yv[0] = make_float4(o[0], o[1], o[2], o[3]);
            Yv[1] = make_float4(o[4], o[5], o[6], o[7]);
        }
    }
}

// ---------------- launch ----------------
extern "C" void kernel_launch(void* const* d_in, const int* in_sizes, int n_in,
                              void* d_out, int out_size)
{
    const float* X0    = (const float*)d_in[0];   // node_embedding [N,128]
    const int*   ei    = (const int*)  d_in[1];   // edge_index [2,E]
    const float* Wrel  = (const float*)d_in[2];   // [L,128,128]
    const float* brel  = (const float*)d_in[3];   // [L,128]
    const float* Wroot = (const float*)d_in[4];   // [L,128,128]
    float* out = (float*)d_out;

    int n = in_sizes[0] / D;
    int e = in_sizes[1] / 2;
    int L = in_sizes[2] / (D * D);

    const int* src = ei;
    const int* dst = ei + e;

    // --- CSR build (dst-sorted adjacency) ---
    zero_deg_kernel<<<(n + 255) / 256, 256>>>(n);
    count_kernel<<<(e + 255) / 256, 256>>>(dst, e);
    int nb = (n + 511) / 512;
    scan_block_kernel<<<nb, 512>>>(n);
    scan_spine_kernel<<<1, 128>>>(nb);
    scan_add_kernel<<<(n + 1 + 255) / 256, 256>>>(n, e);
    fill_kernel<<<(e + 255) / 256, 256>>>(src, dst, e);

    cudaFuncSetAttribute(gemm_elu_kernel,
                         cudaFuncAttributeMaxDynamicSharedMemorySize, GEMM_SMEM);

    int agg_blocks  = (n + 7) / 8;          // 8 warps/block, warp per node
    int gemm_blocks = (n + TM - 1) / TM;

    int xsel = 0;                            // current X: external input
    const float* xext = X0;
    for (int l = 0; l < L; l++) {
        int ysel;
        float* yext;
        if (l == L - 1) { ysel = 0; yext = out; }
        else            { ysel = (l & 1) ? 2 : 1; yext = out; /* unused */ }

        agg_kernel<<<agg_blocks, 256>>>(xext, xsel, n);
        gemm_elu_kernel<<<gemm_blocks, 256, GEMM_SMEM>>>(
            xext, xsel,
            Wrel + (size_t)l * D * D,
            Wroot + (size_t)l * D * D,
            brel + (size_t)l * D,
            yext, ysel, n);

        xsel = ysel;
        xext = yext;
    }
}

// round 6
// speedup vs baseline: 1.1296x; 1.1296x over previous
#include <cuda_runtime.h>
#include <math.h>

#define D 128
#define MAXN 50048
#define MAXE 600064
#define TM 64
#define GEMM_SMEM ((256*128 + 256*TM) * 4)   // 192 KB: W1|W2 + transposed [agg|X] tile

// ---------------- device scratch (no allocations allowed) ----------------
__device__ float g_agg [(size_t)MAXN * D];
__device__ float g_bufA[(size_t)MAXN * D];
__device__ float g_bufB[(size_t)MAXN * D];
__device__ int   g_deg[MAXN];
__device__ int   g_off[MAXN + 1];
__device__ int   g_cursor[MAXN];
__device__ int   g_csr[MAXE];
__device__ int   g_bsum[256];
__device__ float g_invdeg[MAXN];

// buffer selectors: 0 = external pointer, 1 = g_bufA, 2 = g_bufB
static __device__ __forceinline__ const float* sel_src(const float* ext, int s) {
    return (s == 0) ? ext : ((s == 1) ? g_bufA : g_bufB);
}
static __device__ __forceinline__ float* sel_dst(float* ext, int s) {
    return (s == 0) ? ext : ((s == 1) ? g_bufA : g_bufB);
}

// ---------------- packed f32x2 helpers (FFMA2: 2x fp32 FMA throughput) ----
static __device__ __forceinline__ unsigned long long pk2(float x) {
    unsigned long long r;
    asm("mov.b64 %0, {%1, %1};" : "=l"(r) : "f"(x));
    return r;
}
static __device__ __forceinline__ void ffma2(unsigned long long& d,
                                             unsigned long long a,
                                             unsigned long long b) {
    asm("fma.rn.f32x2 %0, %1, %2, %0;" : "+l"(d) : "l"(a), "l"(b));
}
static __device__ __forceinline__ float2 upk(unsigned long long v) {
    float2 r;
    asm("mov.b64 {%0, %1}, %2;" : "=f"(r.x), "=f"(r.y) : "l"(v));
    return r;
}

// ---------------- CSR build ----------------
__global__ void zero_deg_kernel(int n) {
    int i = blockIdx.x * blockDim.x + threadIdx.x;
    if (i < n) g_deg[i] = 0;
}

__global__ void count_kernel(const int* __restrict__ dst, int e) {
    int i = blockIdx.x * blockDim.x + threadIdx.x;
    if (i < e) atomicAdd(&g_deg[dst[i]], 1);
}

// per-512-block exclusive scan over degrees; also emits inv_deg = 1/max(deg,1)
__global__ void scan_block_kernel(int n) {
    __shared__ int s[512];
    int t = threadIdx.x;
    int i = blockIdx.x * 512 + t;
    int v = (i < n) ? g_deg[i] : 0;
    if (i < n) g_invdeg[i] = 1.0f / fmaxf((float)v, 1.0f);
    s[t] = v;
    __syncthreads();
    #pragma unroll
    for (int d = 1; d < 512; d <<= 1) {
        int x = (t >= d) ? s[t - d] : 0;
        __syncthreads();
        s[t] += x;
        __syncthreads();
    }
    if (i < n) g_off[i] = s[t] - v;            // exclusive within block
    if (t == 511) g_bsum[blockIdx.x] = s[511]; // block total
}

// single-block parallel exclusive scan of block sums (nb <= 128)
__global__ void scan_spine_kernel(int nb) {
    __shared__ int s[128];
    int t = threadIdx.x;
    int v = (t < nb) ? g_bsum[t] : 0;
    s[t] = v;
    __syncthreads();
    #pragma unroll
    for (int d = 1; d < 128; d <<= 1) {
        int x = (t >= d) ? s[t - d] : 0;
        __syncthreads();
        s[t] += x;
        __syncthreads();
    }
    if (t < nb) g_bsum[t] = s[t] - v;          // exclusive
}

__global__ void scan_add_kernel(int n, int e) {
    int i = blockIdx.x * blockDim.x + threadIdx.x;
    if (i < n) {
        int o = g_off[i] + g_bsum[i >> 9];
        g_off[i] = o;
        g_cursor[i] = o;
    } else if (i == n) {
        g_off[n] = e;
    }
}

__global__ void fill_kernel(const int* __restrict__ src, const int* __restrict__ dst, int e) {
    int i = blockIdx.x * blockDim.x + threadIdx.x;
    if (i < e) {
        int d = dst[i];
        int p = atomicAdd(&g_cursor[d], 1);
        g_csr[p] = src[i];
    }
}

// ---------------- mean aggregation: one warp per node, float4 lanes --------
__global__ void agg_kernel(const float* __restrict__ Xext, int xsel, int n) {
    const float* X = sel_src(Xext, xsel);
    int warp = blockIdx.x * (blockDim.x >> 5) + (threadIdx.x >> 5);
    int lane = threadIdx.x & 31;
    if (warp >= n) return;
    int s = g_off[warp];
    int e = g_off[warp + 1];
    float4 acc = make_float4(0.f, 0.f, 0.f, 0.f);
    const float4* X4 = (const float4*)X;
    #pragma unroll 4
    for (int k = s; k < e; k++) {
        int j = __ldg(&g_csr[k]);
        float4 v = __ldg(&X4[(size_t)j * 32 + lane]);
        acc.x += v.x; acc.y += v.y; acc.z += v.z; acc.w += v.w;
    }
    float sc = g_invdeg[warp];
    acc.x *= sc; acc.y *= sc; acc.z *= sc; acc.w *= sc;
    ((float4*)g_agg)[(size_t)warp * 32 + lane] = acc;
}

// ---------------- persistent fused GEMM: Y = ELU( agg@W1 + X@W2 + b ) -----
// grid = #SMs, 1 CTA/SM. Weights loaded into SMEM once; CTA loops over
// 64-row tiles, prefetching the next tile into registers during the FFMA2
// main loop and committing via conflict-free STS after a sync.
__global__ __launch_bounds__(256, 1) void gemm_elu_kernel(
    const float* __restrict__ Xext, int xsel,
    const float* __restrict__ W1, const float* __restrict__ W2,
    const float* __restrict__ bias,
    float* __restrict__ Yext, int ysel, int n, int ntiles)
{
    extern __shared__ float smem[];
    float* sW  = smem;                // [256][128] : k<128 -> W1 row k, else W2
    float* sIn = smem + 256 * 128;    // [256][TM]  : transposed [agg|X] tile

    const float* X = sel_src(Xext, xsel);
    float* Y = sel_dst(Yext, ysel);

    int t = threadIdx.x;
    int mrow = (t & 15) * 4;      // 4 rows
    int ncol = (t >> 4) * 8;      // 8 cols = 4 f32x2 pairs

    // ---- load weights ONCE (coalesced, conflict-free) ----
    {
        const float4* W1v = (const float4*)W1;
        const float4* W2v = (const float4*)W2;
        float4* sWv = (float4*)sW;
        #pragma unroll
        for (int i = 0; i < 16; i++) {
            int idx = t + i * 256;          // 0..4095
            sWv[idx]        = __ldg(&W1v[idx]);
            sWv[idx + 4096] = __ldg(&W2v[idx]);
        }
    }

    float b[8];
    #pragma unroll
    for (int j = 0; j < 8; j++) b[j] = __ldg(&bias[ncol + j]);

    // prefetch register staging for one 64-row tile (16 float4 / thread)
    float4 pf[16];

    int tile = blockIdx.x;
    // ---- prologue: fetch first tile ----
    #pragma unroll
    for (int i = 0; i < 16; i++) {
        int idx = t + i * 256;          // 0..4095
        int q   = idx >> 11;            // 0 = agg, 1 = X
        int rem = idx & 2047;
        int m   = rem & 63;             // lane-fastest -> conflict-free STS
        int kv  = rem >> 6;             // float4 column 0..31
        int row = tile * TM + m;
        float4 v = make_float4(0.f, 0.f, 0.f, 0.f);
        const float* srcp = q ? X : g_agg;
        if (tile < ntiles && row < n)
            v = __ldg(&((const float4*)srcp)[(size_t)row * 32 + kv]);
        pf[i] = v;
    }
    #pragma unroll
    for (int i = 0; i < 16; i++) {
        int idx = t + i * 256;
        int q   = idx >> 11;
        int rem = idx & 2047;
        int m   = rem & 63;
        int kv  = rem >> 6;
        int kb  = q * 128 + kv * 4;
        sIn[(kb + 0) * TM + m] = pf[i].x;
        sIn[(kb + 1) * TM + m] = pf[i].y;
        sIn[(kb + 2) * TM + m] = pf[i].z;
        sIn[(kb + 3) * TM + m] = pf[i].w;
    }
    __syncthreads();

    for (; tile < ntiles; tile += gridDim.x) {
        int next = tile + gridDim.x;

        // ---- issue prefetch LDGs for the NEXT tile (hidden under compute) --
        if (next < ntiles) {
            #pragma unroll
            for (int i = 0; i < 16; i++) {
                int idx = t + i * 256;
                int q   = idx >> 11;
                int rem = idx & 2047;
                int m   = rem & 63;
                int kv  = rem >> 6;
                int row = next * TM + m;
                float4 v = make_float4(0.f, 0.f, 0.f, 0.f);
                const float* srcp = q ? X : g_agg;
                if (row < n)
                    v = __ldg(&((const float4*)srcp)[(size_t)row * 32 + kv]);
                pf[i] = v;
            }
        }

        // ---- FFMA2 main loop over K=256 ----
        unsigned long long acc[4][4];
        #pragma unroll
        for (int r = 0; r < 4; r++)
            #pragma unroll
            for (int c = 0; c < 4; c++) acc[r][c] = 0ull;

        const float* aptr = sIn + mrow;
        const unsigned long long* wptr = (const unsigned long long*)(sW + ncol);

        #pragma unroll 4
        for (int k = 0; k < 256; k++) {
            float4 av = *(const float4*)aptr;
            unsigned long long a0 = pk2(av.x), a1 = pk2(av.y),
                               a2 = pk2(av.z), a3 = pk2(av.w);
            unsigned long long w0 = wptr[0], w1 = wptr[1],
                               w2 = wptr[2], w3 = wptr[3];
            ffma2(acc[0][0], a0, w0); ffma2(acc[0][1], a0, w1);
            ffma2(acc[0][2], a0, w2); ffma2(acc[0][3], a0, w3);
            ffma2(acc[1][0], a1, w0); ffma2(acc[1][1], a1, w1);
            ffma2(acc[1][2], a1, w2); ffma2(acc[1][3], a1, w3);
            ffma2(acc[2][0], a2, w0); ffma2(acc[2][1], a2, w1);
            ffma2(acc[2][2], a2, w2); ffma2(acc[2][3], a2, w3);
            ffma2(acc[3][0], a3, w0); ffma2(acc[3][1], a3, w1);
            ffma2(acc[3][2], a3, w2); ffma2(acc[3][3], a3, w3);
            aptr += TM;
            wptr += 64;   // 128 floats = 64 u64
        }

        // ---- epilogue: bias + ELU + store ----
        #pragma unroll
        for (int r = 0; r < 4; r++) {
            int row = tile * TM + mrow + r;
            if (row < n) {
                float o[8];
                #pragma unroll
                for (int c = 0; c < 4; c++) {
                    float2 p = upk(acc[r][c]);
                    o[2 * c]     = p.x + b[2 * c];
                    o[2 * c + 1] = p.y + b[2 * c + 1];
                }
                #pragma unroll
                for (int j = 0; j < 8; j++) {
                    float v = o[j];
                    o[j] = (v > 0.f) ? v : expm1f(v);
                }
                float4* Yv = (float4*)(Y + (size_t)row * D + ncol);
                Yv[0] = make_float4(o[0], o[1], o[2], o[3]);
                Yv[1] = make_float4(o[4], o[5], o[6], o[7]);
            }
        }

        __syncthreads();          // everyone done reading sIn
        if (next < ntiles) {
            #pragma unroll
            for (int i = 0; i < 16; i++) {
                int idx = t + i * 256;
                int q   = idx >> 11;
                int rem = idx & 2047;
                int m   = rem & 63;
                int kv  = rem >> 6;
                int kb  = q * 128 + kv * 4;
                sIn[(kb + 0) * TM + m] = pf[i].x;
                sIn[(kb + 1) * TM + m] = pf[i].y;
                sIn[(kb + 2) * TM + m] = pf[i].z;
                sIn[(kb + 3) * TM + m] = pf[i].w;
            }
        }
        __syncthreads();          // sIn committed for next tile
    }
}

// ---------------- launch ----------------
extern "C" void kernel_launch(void* const* d_in, const int* in_sizes, int n_in,
                              void* d_out, int out_size)
{
    const float* X0    = (const float*)d_in[0];   // node_embedding [N,128]
    const int*   ei    = (const int*)  d_in[1];   // edge_index [2,E]
    const float* Wrel  = (const float*)d_in[2];   // [L,128,128]
    const float* brel  = (const float*)d_in[3];   // [L,128]
    const float* Wroot = (const float*)d_in[4];   // [L,128,128]
    float* out = (float*)d_out;

    int n = in_sizes[0] / D;
    int e = in_sizes[1] / 2;
    int L = in_sizes[2] / (D * D);

    const int* src = ei;
    const int* dst = ei + e;

    // --- CSR build (dst-sorted adjacency) ---
    zero_deg_kernel<<<(n + 255) / 256, 256>>>(n);
    count_kernel<<<(e + 255) / 256, 256>>>(dst, e);
    int nb = (n + 511) / 512;
    scan_block_kernel<<<nb, 512>>>(n);
    scan_spine_kernel<<<1, 128>>>(nb);
    scan_add_kernel<<<(n + 1 + 255) / 256, 256>>>(n, e);
    fill_kernel<<<(e + 255) / 256, 256>>>(src, dst, e);

    cudaFuncSetAttribute(gemm_elu_kernel,
                         cudaFuncAttributeMaxDynamicSharedMemorySize, GEMM_SMEM);

    int nsm = 148;
    {
        int dev = 0, v = 0;
        if (cudaGetDevice(&dev) == cudaSuccess &&
            cudaDeviceGetAttribute(&v, cudaDevAttrMultiProcessorCount, dev) == cudaSuccess &&
            v > 0) nsm = v;
    }

    int agg_blocks = (n + 7) / 8;            // 8 warps/block, warp per node
    int ntiles     = (n + TM - 1) / TM;
    int gemm_grid  = (ntiles < nsm) ? ntiles : nsm;

    int xsel = 0;                            // current X: external input
    const float* xext = X0;
    for (int l = 0; l < L; l++) {
        int ysel;
        float* yext;
        if (l == L - 1) { ysel = 0; yext = out; }
        else            { ysel = (l & 1) ? 2 : 1; yext = out; /* unused */ }

        agg_kernel<<<agg_blocks, 256>>>(xext, xsel, n);
        gemm_elu_kernel<<<gemm_grid, 256, GEMM_SMEM>>>(
            xext, xsel,
            Wrel + (size_t)l * D * D,
            Wroot + (size_t)l * D * D,
            brel + (size_t)l * D,
            yext, ysel, n, ntiles);

        xsel = ysel;
        xext = yext;
    }
}